// round 6
// baseline (speedup 1.0000x reference)
#include <cuda_runtime.h>
#include <cstdint>

#define B_TOK 8192
#define D_IN  1024
#define D_OUT 1024
#define NE    16
#define TOPK  2
#define NH    64

// ---------------- device scratch (static allocations only) ----------------
__device__ int   g_cnt[NE];
__device__ int   g_dst[NE * B_TOK];              // dst slot = token*2 + k
__device__ float g_gw[NE * B_TOK];               // gate weight for that slot
__device__ float g_ybuf[B_TOK * TOPK * D_OUT];   // 64 MB slot-indexed partial outputs

// ---------------- helpers ----------------
__device__ __forceinline__ void cp16(void* s, const void* g) {
    uint32_t sa = (uint32_t)__cvta_generic_to_shared(s);
    asm volatile("cp.async.cg.shared.global [%0], [%1], 16;\n" :: "r"(sa), "l"(g));
}
__device__ __forceinline__ void cp_commit() { asm volatile("cp.async.commit_group;\n"); }
template<int N> __device__ __forceinline__ void cp_wait() {
    asm volatile("cp.async.wait_group %0;\n" :: "n"(N));
}

// packed f32x2 FMA (SASS FFMA2 — only reachable via explicit PTX)
#define FFMA2(acc, a, b) \
    asm("fma.rn.f32x2 %0, %1, %2, %0;" : "+l"(acc) : "l"(a), "l"(b))

__device__ __forceinline__ unsigned long long pk2(float v) {
    unsigned long long r;
    unsigned int u = __float_as_uint(v);
    asm("mov.b64 %0, {%1, %1};" : "=l"(r) : "r"(u));
    return r;
}
__device__ __forceinline__ float2 upk2(unsigned long long p) {
    unsigned int lo, hi;
    asm("mov.b64 {%0, %1}, %2;" : "=r"(lo), "=r"(hi) : "l"(p));
    return make_float2(__uint_as_float(lo), __uint_as_float(hi));
}

__device__ __forceinline__ void top2_insert(float v, int e, float& v0, int& i0,
                                            float& v1, int& i1) {
    if (v > v0 || (v == v0 && e < i0)) { v1 = v0; i1 = i0; v0 = v; i0 = e; }
    else if (v > v1 || (v == v1 && e < i1)) { v1 = v; i1 = e; }
}

// ---------------- kernel 0: reset counters ----------------
__global__ void reset_kernel() {
    if (threadIdx.x < NE) g_cnt[threadIdx.x] = 0;
}

// ---------------- kernel 1: gating + top-2 + expert list append ----------------
// (numerics untouched — top-2 selection must keep matching jax)
__global__ void __launch_bounds__(256) gate_kernel(
    const float* __restrict__ x, const float* __restrict__ Wg,
    const float* __restrict__ bg)
{
    __shared__ float Xs[64][65];
    __shared__ float Wgs[64][16];
    const int tid = threadIdx.x;
    const int tl  = tid >> 2;
    const int eb  = tid & 3;
    const int t0  = blockIdx.x * 64;

    float tot0 = 0.f, tot1 = 0.f, tot2 = 0.f, tot3 = 0.f;

    #pragma unroll 1
    for (int k0 = 0; k0 < D_IN; k0 += 64) {
        #pragma unroll
        for (int i = 0; i < 4; i++) {
            int f = tid + i * 256;
            int r = f >> 4, c4 = f & 15;
            float4 v = *(const float4*)&x[(t0 + r) * D_IN + k0 + c4 * 4];
            Xs[r][c4*4 + 0] = v.x; Xs[r][c4*4 + 1] = v.y;
            Xs[r][c4*4 + 2] = v.z; Xs[r][c4*4 + 3] = v.w;
        }
        {
            int r = tid >> 2, c4 = tid & 3;
            *(float4*)&Wgs[r][c4*4] = *(const float4*)&Wg[(k0 + r) * NE + c4 * 4];
        }
        __syncthreads();
        float a0 = 0.f, a1 = 0.f, a2 = 0.f, a3 = 0.f;
        #pragma unroll 16
        for (int kk = 0; kk < 64; kk++) {
            float xv = Xs[tl][kk];
            float4 w = *(const float4*)&Wgs[kk][eb * 4];
            a0 += xv * w.x; a1 += xv * w.y; a2 += xv * w.z; a3 += xv * w.w;
        }
        tot0 += a0; tot1 += a1; tot2 += a2; tot3 += a3;
        __syncthreads();
    }
    float4 bgv = *(const float4*)&bg[eb * 4];
    tot0 += bgv.x; tot1 += bgv.y; tot2 += bgv.z; tot3 += bgv.w;

    float v0 = -3.402823466e38f, v1 = -3.402823466e38f;
    int   i0 = NE, i1 = NE;
    top2_insert(tot0, eb * 4 + 0, v0, i0, v1, i1);
    top2_insert(tot1, eb * 4 + 1, v0, i0, v1, i1);
    top2_insert(tot2, eb * 4 + 2, v0, i0, v1, i1);
    top2_insert(tot3, eb * 4 + 3, v0, i0, v1, i1);

    const unsigned m = 0xFFFFFFFFu;
    #pragma unroll
    for (int d = 1; d < 4; d <<= 1) {
        float ov0 = __shfl_xor_sync(m, v0, d);
        int   oi0 = __shfl_xor_sync(m, i0, d);
        float ov1 = __shfl_xor_sync(m, v1, d);
        int   oi1 = __shfl_xor_sync(m, i1, d);
        top2_insert(ov0, oi0, v0, i0, v1, i1);
        top2_insert(ov1, oi1, v0, i0, v1, i1);
    }

    if (eb == 0) {
        int tok = t0 + tl;
        float r   = expf(v1 - v0);
        float inv = 1.0f / (1.0f + r);
        int p0 = atomicAdd(&g_cnt[i0], 1);
        g_dst[i0 * B_TOK + p0] = tok * 2;
        g_gw [i0 * B_TOK + p0] = inv;
        int p1 = atomicAdd(&g_cnt[i1], 1);
        g_dst[i1 * B_TOK + p1] = tok * 2 + 1;
        g_gw [i1 * B_TOK + p1] = r * inv;
    }
}

// ---------------- kernel 2: grouped expert MLP (FFMA2 version) ----------------
// grid = (128 token-tiles, 16 experts), block = 256, dyn smem = 82944 B
// smem float offsets:
//   Hs  : 0       [64][68]            4352
//   Xs  : 4352    [2][64][36]         4608   (phase A, padded rows)
//   W1s : 8960    [2][32][64]         4096   (phase A)
//   W2s : 4352    [2][64][128]       16384   (phase B, overlaps A)
#define XP 36
#define HP 68
__global__ void __launch_bounds__(256, 2) expert_kernel(
    const float* __restrict__ x,  const float* __restrict__ W1,
    const float* __restrict__ b1, const float* __restrict__ W2,
    const float* __restrict__ b2)
{
    const int e    = blockIdx.y;
    const int n    = g_cnt[e];
    const int base = blockIdx.x * 64;
    if (base >= n) return;
    const int tid = threadIdx.x;

    __shared__ int   s_dst[64];
    __shared__ int   s_tok[64];
    __shared__ float s_w[64];
    extern __shared__ float sm[];
    float* Hs  = sm;
    float* Xs  = sm + 4352;
    float* W1s = sm + 8960;
    float* W2s = sm + 4352;

    if (tid < 64) {
        int slot = base + tid;
        if (slot < n) {
            int d = g_dst[e * B_TOK + slot];
            s_dst[tid] = d; s_tok[tid] = d >> 1;
            s_w[tid] = g_gw[e * B_TOK + slot];
        } else { s_dst[tid] = -1; s_tok[tid] = 0; s_w[tid] = 0.f; }
    }
    __syncthreads();

    const int ty = tid >> 3;        // 0..31 : token pair
    const int tx = tid & 7;         // 0..7  : col group
    const int r0 = ty * 2;

    // ======== Phase A: H[64][64] = relu(Xg[64][1024] @ W1[e] + b1[e]) ========
    // thread tile: 2 tokens x 8 cols (cols tx*4..+3 and 32+tx*4..+3)
    unsigned long long accA[2][4];
    #pragma unroll
    for (int r = 0; r < 2; r++)
        #pragma unroll
        for (int p = 0; p < 4; p++) accA[r][p] = 0ull;

    auto loadA = [&](int c, int s) {
        const int k0 = c * 32;
        #pragma unroll
        for (int i = 0; i < 2; i++) {
            int f = tid + i * 256;               // 512 float4: Xs
            int t = f >> 3, c4 = f & 7;
            cp16(&Xs[s * 2304 + t * XP + c4 * 4],
                 &x[s_tok[t] * D_IN + k0 + c4 * 4]);
        }
        #pragma unroll
        for (int i = 0; i < 2; i++) {
            int f = tid + i * 256;               // 512 float4: W1s
            int kc = f >> 4, c4 = f & 15;
            cp16(&W1s[s * 2048 + kc * 64 + c4 * 4],
                 &W1[(e * D_IN + k0 + kc) * NH + c4 * 4]);
        }
    };

    loadA(0, 0); cp_commit();
    loadA(1, 1); cp_commit();
    #pragma unroll 1
    for (int c = 0; c < 32; c++) {
        cp_wait<1>(); __syncthreads();
        const float* Xp = Xs  + (c & 1) * 2304;
        const float* Wp = W1s + (c & 1) * 2048;
        #pragma unroll
        for (int kk = 0; kk < 32; kk += 4) {
            float4 xa = *(const float4*)&Xp[ r0      * XP + kk];
            float4 xb = *(const float4*)&Xp[(r0 + 1) * XP + kk];
            #pragma unroll
            for (int q = 0; q < 4; q++) {
                float xva = (q == 0) ? xa.x : (q == 1) ? xa.y : (q == 2) ? xa.z : xa.w;
                float xvb = (q == 0) ? xb.x : (q == 1) ? xb.y : (q == 2) ? xb.z : xb.w;
                unsigned long long X0 = pk2(xva);
                unsigned long long X1 = pk2(xvb);
                ulonglong2 wA = *(const ulonglong2*)&Wp[(kk + q) * 64 + tx * 4];
                ulonglong2 wB = *(const ulonglong2*)&Wp[(kk + q) * 64 + tx * 4 + 32];
                FFMA2(accA[0][0], X0, wA.x); FFMA2(accA[0][1], X0, wA.y);
                FFMA2(accA[0][2], X0, wB.x); FFMA2(accA[0][3], X0, wB.y);
                FFMA2(accA[1][0], X1, wA.x); FFMA2(accA[1][1], X1, wA.y);
                FFMA2(accA[1][2], X1, wB.x); FFMA2(accA[1][3], X1, wB.y);
            }
        }
        __syncthreads();
        if (c + 2 < 32) loadA(c + 2, c & 1);
        cp_commit();
    }

    // bias + relu -> Hs
    {
        float4 bA = *(const float4*)&b1[e * NH + tx * 4];
        float4 bB = *(const float4*)&b1[e * NH + tx * 4 + 32];
        #pragma unroll
        for (int r = 0; r < 2; r++) {
            float2 p0 = upk2(accA[r][0]), p1 = upk2(accA[r][1]);
            float2 p2 = upk2(accA[r][2]), p3 = upk2(accA[r][3]);
            float4 h0, h1;
            h0.x = fmaxf(p0.x + bA.x, 0.f); h0.y = fmaxf(p0.y + bA.y, 0.f);
            h0.z = fmaxf(p1.x + bA.z, 0.f); h0.w = fmaxf(p1.y + bA.w, 0.f);
            h1.x = fmaxf(p2.x + bB.x, 0.f); h1.y = fmaxf(p2.y + bB.y, 0.f);
            h1.z = fmaxf(p3.x + bB.z, 0.f); h1.w = fmaxf(p3.y + bB.w, 0.f);
            *(float4*)&Hs[(r0 + r) * HP + tx * 4]      = h0;
            *(float4*)&Hs[(r0 + r) * HP + tx * 4 + 32] = h1;
        }
    }
    __syncthreads();

    // ======== Phase B: Y[64][1024] = w * (H @ W2[e] + b2[e]) -> ybuf slots ========
    // thread tile: 2 tokens x 16 cols (cols oc0 + tx*4 + j*32, j=0..3)
    auto loadB = [&](int c, int s) {
        const int oc0 = c * 128;
        #pragma unroll
        for (int i = 0; i < 8; i++) {
            int f = tid + i * 256;               // 2048 float4: W2s
            int hh = f >> 5, c4 = f & 31;
            cp16(&W2s[s * 8192 + hh * 128 + c4 * 4],
                 &W2[(e * NH + hh) * D_OUT + oc0 + c4 * 4]);
        }
    };

    loadB(0, 0); cp_commit();
    loadB(1, 1); cp_commit();
    #pragma unroll 1
    for (int c = 0; c < 8; c++) {
        cp_wait<1>(); __syncthreads();
        unsigned long long accB[2][8];
        #pragma unroll
        for (int r = 0; r < 2; r++)
            #pragma unroll
            for (int p = 0; p < 8; p++) accB[r][p] = 0ull;

        const float* Wp = W2s + (c & 1) * 8192;
        #pragma unroll 4
        for (int hh4 = 0; hh4 < 64; hh4 += 4) {
            float4 h0 = *(const float4*)&Hs[ r0      * HP + hh4];
            float4 h1 = *(const float4*)&Hs[(r0 + 1) * HP + hh4];
            #pragma unroll
            for (int q = 0; q < 4; q++) {
                float hv0 = (q == 0) ? h0.x : (q == 1) ? h0.y : (q == 2) ? h0.z : h0.w;
                float hv1 = (q == 0) ? h1.x : (q == 1) ? h1.y : (q == 2) ? h1.z : h1.w;
                unsigned long long H0 = pk2(hv0);
                unsigned long long H1 = pk2(hv1);
                const float* wrow = &Wp[(hh4 + q) * 128 + tx * 4];
                ulonglong2 w0 = *(const ulonglong2*)&wrow[0];
                ulonglong2 w1 = *(const ulonglong2*)&wrow[32];
                ulonglong2 w2 = *(const ulonglong2*)&wrow[64];
                ulonglong2 w3 = *(const ulonglong2*)&wrow[96];
                FFMA2(accB[0][0], H0, w0.x); FFMA2(accB[0][1], H0, w0.y);
                FFMA2(accB[0][2], H0, w1.x); FFMA2(accB[0][3], H0, w1.y);
                FFMA2(accB[0][4], H0, w2.x); FFMA2(accB[0][5], H0, w2.y);
                FFMA2(accB[0][6], H0, w3.x); FFMA2(accB[0][7], H0, w3.y);
                FFMA2(accB[1][0], H1, w0.x); FFMA2(accB[1][1], H1, w0.y);
                FFMA2(accB[1][2], H1, w1.x); FFMA2(accB[1][3], H1, w1.y);
                FFMA2(accB[1][4], H1, w2.x); FFMA2(accB[1][5], H1, w2.y);
                FFMA2(accB[1][6], H1, w3.x); FFMA2(accB[1][7], H1, w3.y);
            }
        }
        // epilogue: + b2, * gate weight, store to slot
        const int oc0 = c * 128;
        #pragma unroll
        for (int j = 0; j < 4; j++) {
            int cc = oc0 + tx * 4 + j * 32;
            float4 bb = *(const float4*)&b2[e * D_OUT + cc];
            #pragma unroll
            for (int r = 0; r < 2; r++) {
                int dst = s_dst[r0 + r];
                if (dst >= 0) {
                    float w = s_w[r0 + r];
                    float2 pa = upk2(accB[r][j * 2]);
                    float2 pb = upk2(accB[r][j * 2 + 1]);
                    float4 o;
                    o.x = w * (pa.x + bb.x); o.y = w * (pa.y + bb.y);
                    o.z = w * (pb.x + bb.z); o.w = w * (pb.y + bb.w);
                    *(float4*)&g_ybuf[dst * D_OUT + cc] = o;
                }
            }
        }
        __syncthreads();
        if (c + 2 < 8) loadB(c + 2, c & 1);
        cp_commit();
    }
}

// ---------------- kernel 3: combine the two expert contributions ----------------
__global__ void __launch_bounds__(256) combine_kernel(float* __restrict__ out) {
    int idx = blockIdx.x * 256 + threadIdx.x;
    int t = idx >> 8;
    int c = idx & 255;
    float4 a = *((const float4*)&g_ybuf[(t * 2    ) * D_OUT] + c);
    float4 b = *((const float4*)&g_ybuf[(t * 2 + 1) * D_OUT] + c);
    float4 r;
    r.x = a.x + b.x; r.y = a.y + b.y; r.z = a.z + b.z; r.w = a.w + b.w;
    ((float4*)out)[idx] = r;
}

// ---------------- launch ----------------
extern "C" void kernel_launch(void* const* d_in, const int* in_sizes, int n_in,
                              void* d_out, int out_size) {
    const float* x  = (const float*)d_in[0];
    const float* Wg = (const float*)d_in[1];
    const float* bg = (const float*)d_in[2];
    const float* W1 = (const float*)d_in[3];
    const float* b1 = (const float*)d_in[4];
    const float* W2 = (const float*)d_in[5];
    const float* b2 = (const float*)d_in[6];
    float* out = (float*)d_out;

    cudaFuncSetAttribute(expert_kernel,
                         cudaFuncAttributeMaxDynamicSharedMemorySize, 82944);

    reset_kernel<<<1, 32>>>();
    gate_kernel<<<B_TOK / 64, 256>>>(x, Wg, bg);
    expert_kernel<<<dim3(128, NE), 256, 82944>>>(x, W1, b1, W2, b2);
    combine_kernel<<<(B_TOK * D_OUT / 4) / 256, 256>>>(out);
}

// round 8
// speedup vs baseline: 1.6857x; 1.6857x over previous
#include <cuda_runtime.h>
#include <cuda_bf16.h>
#include <cstdint>

#define B_TOK 8192
#define D_IN  1024
#define D_OUT 1024
#define NE    16
#define TOPK  2
#define NH    64
#define TILE_M 128

// ---------------- device scratch (static allocations only) ----------------
__device__ int   g_cnt[NE];
__device__ int   g_dst[NE * B_TOK];
__device__ float g_gw[NE * B_TOK];
__device__ float g_ybuf[B_TOK * TOPK * D_OUT];

// bf16 hi/lo split weights (same layout as source, no transpose)
__device__ __nv_bfloat16 g_W1s_hi[NE * D_IN * NH];    // [e][k][h]
__device__ __nv_bfloat16 g_W1s_lo[NE * D_IN * NH];
__device__ __nv_bfloat16 g_W2s_hi[NE * NH * D_OUT];   // [e][h][o]
__device__ __nv_bfloat16 g_W2s_lo[NE * NH * D_OUT];

// ---------------- helpers ----------------
__device__ __forceinline__ uint32_t smem_u32(const void* p) {
    uint32_t a;
    asm("{ .reg .u64 t; cvta.to.shared.u64 t, %1; cvt.u32.u64 %0, t; }" : "=r"(a) : "l"(p));
    return a;
}
__device__ __forceinline__ void cp16s(uint32_t sa, const void* g) {
    asm volatile("cp.async.cg.shared.global [%0], [%1], 16;\n" :: "r"(sa), "l"(g));
}
__device__ __forceinline__ void cp_commit() { asm volatile("cp.async.commit_group;\n"); }
template<int N> __device__ __forceinline__ void cp_wait() {
    asm volatile("cp.async.wait_group %0;\n" :: "n"(N));
}
__device__ __forceinline__ void sts128(uint32_t a, uint32_t r0, uint32_t r1,
                                       uint32_t r2, uint32_t r3) {
    asm volatile("st.shared.v4.b32 [%0], {%1,%2,%3,%4};"
                 :: "r"(a), "r"(r0), "r"(r1), "r"(r2), "r"(r3) : "memory");
}
__device__ __forceinline__ void ldsm4(uint32_t a, uint32_t* r) {
    asm volatile("ldmatrix.sync.aligned.m8n8.x4.shared.b16 {%0,%1,%2,%3}, [%4];"
                 : "=r"(r[0]), "=r"(r[1]), "=r"(r[2]), "=r"(r[3]) : "r"(a));
}
__device__ __forceinline__ void ldsm4t(uint32_t a, uint32_t* r) {
    asm volatile("ldmatrix.sync.aligned.m8n8.x4.trans.shared.b16 {%0,%1,%2,%3}, [%4];"
                 : "=r"(r[0]), "=r"(r[1]), "=r"(r[2]), "=r"(r[3]) : "r"(a));
}
__device__ __forceinline__ void mma16816(float* d, const uint32_t* a, const uint32_t* b) {
    asm volatile("mma.sync.aligned.m16n8k16.row.col.f32.bf16.bf16.f32 "
                 "{%0,%1,%2,%3}, {%4,%5,%6,%7}, {%8,%9}, {%0,%1,%2,%3};"
                 : "+f"(d[0]), "+f"(d[1]), "+f"(d[2]), "+f"(d[3])
                 : "r"(a[0]), "r"(a[1]), "r"(a[2]), "r"(a[3]), "r"(b[0]), "r"(b[1]));
}

// pack (lo half = f0, hi half = f1) into bf16x2
__device__ __forceinline__ uint32_t pk_bf(float f0, float f1) {
    uint32_t r;
    asm("cvt.rn.bf16x2.f32 %0, %1, %2;" : "=r"(r) : "f"(f1), "f"(f0));
    return r;
}
__device__ __forceinline__ float bf_lo_f(uint32_t p) { return __uint_as_float(p << 16); }
__device__ __forceinline__ float bf_hi_f(uint32_t p) { return __uint_as_float(p & 0xFFFF0000u); }

__device__ __forceinline__ void top2_insert(float v, int e, float& v0, int& i0,
                                            float& v1, int& i1) {
    if (v > v0 || (v == v0 && e < i0)) { v1 = v0; i1 = i0; v0 = v; i0 = e; }
    else if (v > v1 || (v == v1 && e < i1)) { v1 = v; i1 = e; }
}

// ---------------- kernel 0: reset counters ----------------
__global__ void reset_kernel() {
    if (threadIdx.x < NE) g_cnt[threadIdx.x] = 0;
}

// ---------------- kernel: hi/lo split (no transpose) ----------------
__global__ void __launch_bounds__(256) split_kernel(
    const float* __restrict__ src, __nv_bfloat16* __restrict__ hi,
    __nv_bfloat16* __restrict__ lo, int n)
{
    int i = blockIdx.x * 256 + threadIdx.x;
    if (i < n) {
        float v = src[i];
        __nv_bfloat16 h = __float2bfloat16_rn(v);
        hi[i] = h;
        lo[i] = __float2bfloat16_rn(v - __bfloat162float(h));
    }
}

// ---------------- kernel 1: gating (unchanged, validated) ----------------
__global__ void __launch_bounds__(256) gate_kernel(
    const float* __restrict__ x, const float* __restrict__ Wg,
    const float* __restrict__ bg)
{
    __shared__ float Xs[64][65];
    __shared__ float Wgs[64][16];
    const int tid = threadIdx.x;
    const int tl  = tid >> 2;
    const int eb  = tid & 3;
    const int t0  = blockIdx.x * 64;

    float tot0 = 0.f, tot1 = 0.f, tot2 = 0.f, tot3 = 0.f;

    #pragma unroll 1
    for (int k0 = 0; k0 < D_IN; k0 += 64) {
        #pragma unroll
        for (int i = 0; i < 4; i++) {
            int f = tid + i * 256;
            int r = f >> 4, c4 = f & 15;
            float4 v = *(const float4*)&x[(t0 + r) * D_IN + k0 + c4 * 4];
            Xs[r][c4*4 + 0] = v.x; Xs[r][c4*4 + 1] = v.y;
            Xs[r][c4*4 + 2] = v.z; Xs[r][c4*4 + 3] = v.w;
        }
        {
            int r = tid >> 2, c4 = tid & 3;
            *(float4*)&Wgs[r][c4*4] = *(const float4*)&Wg[(k0 + r) * NE + c4 * 4];
        }
        __syncthreads();
        float a0 = 0.f, a1 = 0.f, a2 = 0.f, a3 = 0.f;
        #pragma unroll 16
        for (int kk = 0; kk < 64; kk++) {
            float xv = Xs[tl][kk];
            float4 w = *(const float4*)&Wgs[kk][eb * 4];
            a0 += xv * w.x; a1 += xv * w.y; a2 += xv * w.z; a3 += xv * w.w;
        }
        tot0 += a0; tot1 += a1; tot2 += a2; tot3 += a3;
        __syncthreads();
    }
    float4 bgv = *(const float4*)&bg[eb * 4];
    tot0 += bgv.x; tot1 += bgv.y; tot2 += bgv.z; tot3 += bgv.w;

    float v0 = -3.402823466e38f, v1 = -3.402823466e38f;
    int   i0 = NE, i1 = NE;
    top2_insert(tot0, eb * 4 + 0, v0, i0, v1, i1);
    top2_insert(tot1, eb * 4 + 1, v0, i0, v1, i1);
    top2_insert(tot2, eb * 4 + 2, v0, i0, v1, i1);
    top2_insert(tot3, eb * 4 + 3, v0, i0, v1, i1);

    const unsigned m = 0xFFFFFFFFu;
    #pragma unroll
    for (int d = 1; d < 4; d <<= 1) {
        float ov0 = __shfl_xor_sync(m, v0, d);
        int   oi0 = __shfl_xor_sync(m, i0, d);
        float ov1 = __shfl_xor_sync(m, v1, d);
        int   oi1 = __shfl_xor_sync(m, i1, d);
        top2_insert(ov0, oi0, v0, i0, v1, i1);
        top2_insert(ov1, oi1, v0, i0, v1, i1);
    }

    if (eb == 0) {
        int tok = t0 + tl;
        float r   = expf(v1 - v0);
        float inv = 1.0f / (1.0f + r);
        int p0 = atomicAdd(&g_cnt[i0], 1);
        g_dst[i0 * B_TOK + p0] = tok * 2;
        g_gw [i0 * B_TOK + p0] = inv;
        int p1 = atomicAdd(&g_cnt[i1], 1);
        g_dst[i1 * B_TOK + p1] = tok * 2 + 1;
        g_gw [i1 * B_TOK + p1] = r * inv;
    }
}

// ---------------- kernel 2: HMMA grouped expert MLP ----------------
// dyn smem (from 1024-aligned base SB), all byte offsets:
//   Hhi @ 0 (18432 = 128 rows * 144B)   Hlo @ 18432          (36864 total)
//   pool @ 36864:
//     Phase A buf b @ pool + b*55296:
//       Xhi(18432: 128r x 144B) Xlo(+18432) W1hi(+36864, 64r x 144B = 9216) W1lo(+46080)
//     Phase B buf b @ pool + b*34816:
//       W2hi(17408: 64r x 272B) W2lo(+17408)
#define SM_POOL 36864
#define SM_DYN  (36864 + 2*55296 + 1024)

__global__ void __launch_bounds__(256, 1) expert_kernel(
    const float* __restrict__ x, const float* __restrict__ b1,
    const float* __restrict__ b2)
{
    const int e    = blockIdx.y;
    const int n    = g_cnt[e];
    const int base = blockIdx.x * TILE_M;
    if (base >= n) return;

    const int tid = threadIdx.x;
    const int wid = tid >> 5, lid = tid & 31;
    const int wm  = wid & 3, wn = wid >> 2;     // warp grid 4(M) x 2(N)

    __shared__ int   s_dst[TILE_M];
    __shared__ int   s_tok[TILE_M];
    __shared__ float s_w[TILE_M];
    extern __shared__ char dynsm[];
    const uint32_t SB = (smem_u32(dynsm) + 1023u) & ~1023u;
    const uint32_t SP = SB + SM_POOL;

    if (tid < TILE_M) {
        int slot = base + tid;
        if (slot < n) {
            int d = g_dst[e * B_TOK + slot];
            s_dst[tid] = d; s_tok[tid] = d >> 1;
            s_w[tid] = g_gw[e * B_TOK + slot];
        } else { s_dst[tid] = -1; s_tok[tid] = 0; s_w[tid] = 0.f; }
    }
    __syncthreads();

    // ================= Phase A: H = relu(X @ W1 + b1) =================
    const int arow = tid >> 1, ahalf = tid & 1;
    const float* xrow = x + (size_t)s_tok[arow] * D_IN + ahalf * 32;
    float4 xr[8];

    auto ldgX = [&](int c) {
        const float* p = xrow + c * 64;
        #pragma unroll
        for (int j = 0; j < 8; j++) xr[j] = *(const float4*)(p + j * 4);
    };
    auto stsX = [&](int b) {
        uint32_t hib = SP + b * 55296;
        uint32_t lob = hib + 18432;
        uint32_t hi[16], lo[16];
        #pragma unroll
        for (int j = 0; j < 8; j++) {
            float f0 = xr[j].x, f1 = xr[j].y, f2 = xr[j].z, f3 = xr[j].w;
            uint32_t h0 = pk_bf(f0, f1), h1 = pk_bf(f2, f3);
            hi[2*j] = h0; hi[2*j+1] = h1;
            lo[2*j]   = pk_bf(f0 - bf_lo_f(h0), f1 - bf_hi_f(h0));
            lo[2*j+1] = pk_bf(f2 - bf_lo_f(h1), f3 - bf_hi_f(h1));
        }
        uint32_t rb = arow * 144 + ahalf * 64;
        #pragma unroll
        for (int q = 0; q < 4; q++) {
            sts128(hib + rb + q * 16, hi[4*q], hi[4*q+1], hi[4*q+2], hi[4*q+3]);
            sts128(lob + rb + q * 16, lo[4*q], lo[4*q+1], lo[4*q+2], lo[4*q+3]);
        }
    };
    auto cpW1 = [&](int c, int b) {
        uint32_t hib = SP + b * 55296 + 36864;
        uint32_t lob = hib + 9216;
        #pragma unroll
        for (int i = 0; i < 2; i++) {
            int f = tid + i * 256;               // 0..511
            int r = f >> 3, s = f & 7;
            uint32_t off = r * 144 + s * 16;
            int gi = (e * D_IN + c * 64 + r) * NH + s * 8;
            cp16s(hib + off, &g_W1s_hi[gi]);
            cp16s(lob + off, &g_W1s_lo[gi]);
        }
    };

    float accA[2][4][4];
    #pragma unroll
    for (int mb = 0; mb < 2; mb++)
        #pragma unroll
        for (int nb = 0; nb < 4; nb++)
            #pragma unroll
            for (int q = 0; q < 4; q++) accA[mb][nb][q] = 0.f;

    auto computeA = [&](int b) {
        uint32_t Xb = SP + b * 55296;
        uint32_t Wb = Xb + 36864;
        #pragma unroll
        for (int ks = 0; ks < 4; ks++) {
            uint32_t ah[2][4], al[2][4];
            #pragma unroll
            for (int mb = 0; mb < 2; mb++) {
                uint32_t ad = Xb + (wm*32 + mb*16 + (lid & 15)) * 144
                            + ks * 32 + ((lid >> 4) << 4);
                ldsm4(ad, ah[mb]);
                ldsm4(ad + 18432, al[mb]);
            }
            #pragma unroll
            for (int j = 0; j < 2; j++) {
                uint32_t bd = Wb + (ks*16 + (lid & 15)) * 144
                            + (wn*32 + j*16 + ((lid >> 4) << 3)) * 2;
                uint32_t bh[4], bl[4];
                ldsm4t(bd, bh);
                ldsm4t(bd + 9216, bl);
                #pragma unroll
                for (int mb = 0; mb < 2; mb++)
                    #pragma unroll
                    for (int nn = 0; nn < 2; nn++) {
                        int nb = j*2 + nn;
                        mma16816(accA[mb][nb], ah[mb], bh + nn*2);
                        mma16816(accA[mb][nb], ah[mb], bl + nn*2);
                        mma16816(accA[mb][nb], al[mb], bh + nn*2);
                    }
            }
        }
    };

    ldgX(0);
    stsX(0);
    cpW1(0, 0); cp_commit();
    ldgX(1);
    cp_wait<0>(); __syncthreads();
    #pragma unroll 1
    for (int c = 0; c < 16; c++) {
        const int b = c & 1;
        if (c < 15) {
            stsX(b ^ 1);                      // xr holds chunk c+1
            cpW1(c + 1, b ^ 1); cp_commit();
            if (c < 14) ldgX(c + 2);
        }
        computeA(b);
        if (c < 15) { cp_wait<0>(); __syncthreads(); }
    }

    // ---- epilogue A: bias + relu -> bf16 hi/lo H tiles ----
    {
        char* SBp = dynsm + (SB - smem_u32(dynsm));
        #pragma unroll
        for (int mb = 0; mb < 2; mb++) {
            int r = wm*32 + mb*16 + (lid >> 2);
            #pragma unroll
            for (int nb = 0; nb < 4; nb++) {
                int col = wn*32 + nb*8 + (lid & 3) * 2;
                float bb0 = b1[e * NH + col], bb1 = b1[e * NH + col + 1];
                float v0 = fmaxf(accA[mb][nb][0] + bb0, 0.f);
                float v1 = fmaxf(accA[mb][nb][1] + bb1, 0.f);
                uint32_t h = pk_bf(v0, v1);
                uint32_t l = pk_bf(v0 - bf_lo_f(h), v1 - bf_hi_f(h));
                *(uint32_t*)(SBp + r * 144 + col * 2)         = h;
                *(uint32_t*)(SBp + 18432 + r * 144 + col * 2) = l;
                v0 = fmaxf(accA[mb][nb][2] + bb0, 0.f);
                v1 = fmaxf(accA[mb][nb][3] + bb1, 0.f);
                h = pk_bf(v0, v1);
                l = pk_bf(v0 - bf_lo_f(h), v1 - bf_hi_f(h));
                *(uint32_t*)(SBp + (r + 8) * 144 + col * 2)         = h;
                *(uint32_t*)(SBp + 18432 + (r + 8) * 144 + col * 2) = l;
            }
        }
    }
    __syncthreads();

    // ================= Phase B: Y = w * (H @ W2 + b2) =================
    auto cpW2 = [&](int cn, int b) {
        uint32_t hib = SP + b * 34816;
        uint32_t lob = hib + 17408;
        #pragma unroll
        for (int i = 0; i < 4; i++) {
            int f = tid + i * 256;               // 0..1023
            int r = f >> 4, s = f & 15;
            uint32_t off = r * 272 + s * 16;
            int gi = (e * NH + r) * D_OUT + cn * 128 + s * 8;
            cp16s(hib + off, &g_W2s_hi[gi]);
            cp16s(lob + off, &g_W2s_lo[gi]);
        }
    };

    cpW2(0, 0); cp_commit();
    cp_wait<0>(); __syncthreads();
    #pragma unroll 1
    for (int cn = 0; cn < 8; cn++) {
        const int b = cn & 1;
        if (cn < 7) { cpW2(cn + 1, b ^ 1); cp_commit(); }

        float accB[2][8][4];
        #pragma unroll
        for (int mb = 0; mb < 2; mb++)
            #pragma unroll
            for (int nb = 0; nb < 8; nb++)
                #pragma unroll
                for (int q = 0; q < 4; q++) accB[mb][nb][q] = 0.f;

        uint32_t Wb = SP + b * 34816;
        #pragma unroll
        for (int ks = 0; ks < 4; ks++) {
            uint32_t ah[2][4], al[2][4];
            #pragma unroll
            for (int mb = 0; mb < 2; mb++) {
                uint32_t ad = SB + (wm*32 + mb*16 + (lid & 15)) * 144
                            + ks * 32 + ((lid >> 4) << 4);
                ldsm4(ad, ah[mb]);
                ldsm4(ad + 18432, al[mb]);
            }
            #pragma unroll
            for (int j = 0; j < 4; j++) {
                uint32_t bd = Wb + (ks*16 + (lid & 15)) * 272
                            + (wn*64 + j*16 + ((lid >> 4) << 3)) * 2;
                uint32_t bh[4], bl[4];
                ldsm4t(bd, bh);
                ldsm4t(bd + 17408, bl);
                #pragma unroll
                for (int mb = 0; mb < 2; mb++)
                    #pragma unroll
                    for (int nn = 0; nn < 2; nn++) {
                        int nb = j*2 + nn;
                        mma16816(accB[mb][nb], ah[mb], bh + nn*2);
                        mma16816(accB[mb][nb], ah[mb], bl + nn*2);
                        mma16816(accB[mb][nb], al[mb], bh + nn*2);
                    }
            }
        }

        // epilogue: + b2, * gate weight, scatter to ybuf slots
        #pragma unroll
        for (int mb = 0; mb < 2; mb++) {
            int r  = wm*32 + mb*16 + (lid >> 2);
            int d0 = s_dst[r],     d1 = s_dst[r + 8];
            float w0 = s_w[r],     w1 = s_w[r + 8];
            #pragma unroll
            for (int nb = 0; nb < 8; nb++) {
                int col = cn*128 + wn*64 + nb*8 + (lid & 3) * 2;
                float bb0 = b2[e * D_OUT + col], bb1 = b2[e * D_OUT + col + 1];
                if (d0 >= 0) {
                    float2 o;
                    o.x = w0 * (accB[mb][nb][0] + bb0);
                    o.y = w0 * (accB[mb][nb][1] + bb1);
                    *(float2*)&g_ybuf[(size_t)d0 * D_OUT + col] = o;
                }
                if (d1 >= 0) {
                    float2 o;
                    o.x = w1 * (accB[mb][nb][2] + bb0);
                    o.y = w1 * (accB[mb][nb][3] + bb1);
                    *(float2*)&g_ybuf[(size_t)d1 * D_OUT + col] = o;
                }
            }
        }
        if (cn < 7) { cp_wait<0>(); __syncthreads(); }
    }
}

// ---------------- kernel 3: combine ----------------
__global__ void __launch_bounds__(256) combine_kernel(float* __restrict__ out) {
    int idx = blockIdx.x * 256 + threadIdx.x;
    int t = idx >> 8;
    int c = idx & 255;
    float4 a = *((const float4*)&g_ybuf[(t * 2    ) * D_OUT] + c);
    float4 b = *((const float4*)&g_ybuf[(t * 2 + 1) * D_OUT] + c);
    float4 r;
    r.x = a.x + b.x; r.y = a.y + b.y; r.z = a.z + b.z; r.w = a.w + b.w;
    ((float4*)out)[idx] = r;
}

// ---------------- launch ----------------
extern "C" void kernel_launch(void* const* d_in, const int* in_sizes, int n_in,
                              void* d_out, int out_size) {
    const float* x  = (const float*)d_in[0];
    const float* Wg = (const float*)d_in[1];
    const float* bg = (const float*)d_in[2];
    const float* W1 = (const float*)d_in[3];
    const float* b1 = (const float*)d_in[4];
    const float* W2 = (const float*)d_in[5];
    const float* b2 = (const float*)d_in[6];
    float* out = (float*)d_out;

    cudaFuncSetAttribute(expert_kernel,
                         cudaFuncAttributeMaxDynamicSharedMemorySize, SM_DYN);

    __nv_bfloat16 *w1hi, *w1lo, *w2hi, *w2lo;
    cudaGetSymbolAddress((void**)&w1hi, g_W1s_hi);
    cudaGetSymbolAddress((void**)&w1lo, g_W1s_lo);
    cudaGetSymbolAddress((void**)&w2hi, g_W2s_hi);
    cudaGetSymbolAddress((void**)&w2lo, g_W2s_lo);

    reset_kernel<<<1, 32>>>();
    const int NW = NE * D_IN * NH;
    split_kernel<<<(NW + 255) / 256, 256>>>(W1, w1hi, w1lo, NW);
    split_kernel<<<(NW + 255) / 256, 256>>>(W2, w2hi, w2lo, NW);
    gate_kernel<<<B_TOK / 64, 256>>>(x, Wg, bg);
    expert_kernel<<<dim3(B_TOK / TILE_M, NE), 256, SM_DYN>>>(x, b1, b2);
    combine_kernel<<<(B_TOK * D_OUT / 4) / 256, 256>>>(out);
}

// round 9
// speedup vs baseline: 1.9231x; 1.1408x over previous
#include <cuda_runtime.h>
#include <cuda_bf16.h>
#include <cstdint>

#define B_TOK 8192
#define D_IN  1024
#define D_OUT 1024
#define NE    16
#define TOPK  2
#define NH    64
#define TILE_M 128

// ---------------- device scratch (static allocations only) ----------------
__device__ int   g_cnt[NE];
__device__ int   g_dst[NE * B_TOK];
__device__ float g_gw[NE * B_TOK];
__device__ float g_ybuf[B_TOK * TOPK * D_OUT];

// bf16 hi/lo split weights (same layout as source, no transpose)
__device__ __nv_bfloat16 g_W1s_hi[NE * D_IN * NH];    // [e][k][h]
__device__ __nv_bfloat16 g_W1s_lo[NE * D_IN * NH];
__device__ __nv_bfloat16 g_W2s_hi[NE * NH * D_OUT];   // [e][h][o]
__device__ __nv_bfloat16 g_W2s_lo[NE * NH * D_OUT];

// ---------------- helpers ----------------
__device__ __forceinline__ uint32_t smem_u32(const void* p) {
    uint32_t a;
    asm("{ .reg .u64 t; cvta.to.shared.u64 t, %1; cvt.u32.u64 %0, t; }" : "=r"(a) : "l"(p));
    return a;
}
__device__ __forceinline__ void cp16s(uint32_t sa, const void* g) {
    asm volatile("cp.async.cg.shared.global [%0], [%1], 16;\n" :: "r"(sa), "l"(g));
}
__device__ __forceinline__ void cp_commit() { asm volatile("cp.async.commit_group;\n"); }
template<int N> __device__ __forceinline__ void cp_wait() {
    asm volatile("cp.async.wait_group %0;\n" :: "n"(N));
}
__device__ __forceinline__ void sts128(uint32_t a, uint32_t r0, uint32_t r1,
                                       uint32_t r2, uint32_t r3) {
    asm volatile("st.shared.v4.b32 [%0], {%1,%2,%3,%4};"
                 :: "r"(a), "r"(r0), "r"(r1), "r"(r2), "r"(r3) : "memory");
}
__device__ __forceinline__ void ldsm4(uint32_t a, uint32_t* r) {
    asm volatile("ldmatrix.sync.aligned.m8n8.x4.shared.b16 {%0,%1,%2,%3}, [%4];"
                 : "=r"(r[0]), "=r"(r[1]), "=r"(r[2]), "=r"(r[3]) : "r"(a));
}
__device__ __forceinline__ void ldsm4t(uint32_t a, uint32_t* r) {
    asm volatile("ldmatrix.sync.aligned.m8n8.x4.trans.shared.b16 {%0,%1,%2,%3}, [%4];"
                 : "=r"(r[0]), "=r"(r[1]), "=r"(r[2]), "=r"(r[3]) : "r"(a));
}
__device__ __forceinline__ void mma16816(float* d, const uint32_t* a, const uint32_t* b) {
    asm volatile("mma.sync.aligned.m16n8k16.row.col.f32.bf16.bf16.f32 "
                 "{%0,%1,%2,%3}, {%4,%5,%6,%7}, {%8,%9}, {%0,%1,%2,%3};"
                 : "+f"(d[0]), "+f"(d[1]), "+f"(d[2]), "+f"(d[3])
                 : "r"(a[0]), "r"(a[1]), "r"(a[2]), "r"(a[3]), "r"(b[0]), "r"(b[1]));
}

// pack (lo half = f0, hi half = f1) into bf16x2
__device__ __forceinline__ uint32_t pk_bf(float f0, float f1) {
    uint32_t r;
    asm("cvt.rn.bf16x2.f32 %0, %1, %2;" : "=r"(r) : "f"(f1), "f"(f0));
    return r;
}
__device__ __forceinline__ float bf_lo_f(uint32_t p) { return __uint_as_float(p << 16); }
__device__ __forceinline__ float bf_hi_f(uint32_t p) { return __uint_as_float(p & 0xFFFF0000u); }

__device__ __forceinline__ void top2_insert(float v, int e, float& v0, int& i0,
                                            float& v1, int& i1) {
    if (v > v0 || (v == v0 && e < i0)) { v1 = v0; i1 = i0; v0 = v; i0 = e; }
    else if (v > v1 || (v == v1 && e < i1)) { v1 = v; i1 = e; }
}

// ---------------- kernel 0: reset counters ----------------
__global__ void reset_kernel() {
    if (threadIdx.x < NE) g_cnt[threadIdx.x] = 0;
}

// ---------------- kernel: hi/lo split (no transpose) ----------------
__global__ void __launch_bounds__(256) split_kernel(
    const float* __restrict__ src, __nv_bfloat16* __restrict__ hi,
    __nv_bfloat16* __restrict__ lo, int n)
{
    int i = blockIdx.x * 256 + threadIdx.x;
    if (i < n) {
        float v = src[i];
        __nv_bfloat16 h = __float2bfloat16_rn(v);
        hi[i] = h;
        lo[i] = __float2bfloat16_rn(v - __bfloat162float(h));
    }
}

// ---------------- kernel 1: gating + top-2 + append ----------------
// block = 128 threads = 32 tokens x 4 expert-quads; grid = 8192/32 = 256
// cp.async double-buffered chunk loads; per-expert summation order is
// bitwise-identical to the validated R5 gate (chunk-local accumulators,
// sequential kk within chunk).
#define GT 32
__global__ void __launch_bounds__(128) gate_kernel(
    const float* __restrict__ x, const float* __restrict__ Wg,
    const float* __restrict__ bg)
{
    __shared__ float Xs[2][GT][68];    // padded rows (272B, 16B granular)
    __shared__ float Wgs[2][64][16];
    const int tid = threadIdx.x;
    const int tl  = tid >> 2;          // token-in-block 0..31
    const int eb  = tid & 3;           // expert quad 0..3
    const int t0  = blockIdx.x * GT;

    const uint32_t xs_b  = smem_u32(&Xs[0][0][0]);
    const uint32_t wgs_b = smem_u32(&Wgs[0][0][0]);

    auto loadX = [&](int c, int b) {
        // 512 float4 tasks / 128 threads = 4 each
        #pragma unroll
        for (int i = 0; i < 4; i++) {
            int f = tid + i * 128;
            int r = f >> 4, c4 = f & 15;
            cp16s(xs_b + (uint32_t)(b * GT * 68 + r * 68 + c4 * 4) * 4,
                  &x[(t0 + r) * D_IN + c * 64 + c4 * 4]);
        }
    };
    auto loadW = [&](int c, int b) {
        // 256 float4 tasks / 128 threads = 2 each
        #pragma unroll
        for (int i = 0; i < 2; i++) {
            int f = tid + i * 128;
            int r = f >> 2, c4 = f & 3;
            cp16s(wgs_b + (uint32_t)(b * 64 * 16 + r * 16 + c4 * 4) * 4,
                  &Wg[(c * 64 + r) * NE + c4 * 4]);
        }
    };

    float tot0 = 0.f, tot1 = 0.f, tot2 = 0.f, tot3 = 0.f;

    loadX(0, 0); loadW(0, 0); cp_commit();
    loadX(1, 1); loadW(1, 1); cp_commit();

    #pragma unroll 1
    for (int c = 0; c < 16; c++) {
        const int b = c & 1;
        cp_wait<1>(); __syncthreads();
        // chunk-local accumulators (identical order to validated gate)
        float a0 = 0.f, a1 = 0.f, a2 = 0.f, a3 = 0.f;
        #pragma unroll 16
        for (int kk = 0; kk < 64; kk++) {
            float xv = Xs[b][tl][kk];
            float4 w = *(const float4*)&Wgs[b][kk][eb * 4];
            a0 += xv * w.x; a1 += xv * w.y; a2 += xv * w.z; a3 += xv * w.w;
        }
        tot0 += a0; tot1 += a1; tot2 += a2; tot3 += a3;
        __syncthreads();
        if (c + 2 < 16) { loadX(c + 2, b); loadW(c + 2, b); }
        cp_commit();
    }

    float4 bgv = *(const float4*)&bg[eb * 4];
    tot0 += bgv.x; tot1 += bgv.y; tot2 += bgv.z; tot3 += bgv.w;

    // local top-2 among my 4 experts (jax tie-break: lower index wins)
    float v0 = -3.402823466e38f, v1 = -3.402823466e38f;
    int   i0 = NE, i1 = NE;
    top2_insert(tot0, eb * 4 + 0, v0, i0, v1, i1);
    top2_insert(tot1, eb * 4 + 1, v0, i0, v1, i1);
    top2_insert(tot2, eb * 4 + 2, v0, i0, v1, i1);
    top2_insert(tot3, eb * 4 + 3, v0, i0, v1, i1);

    const unsigned m = 0xFFFFFFFFu;
    #pragma unroll
    for (int d = 1; d < 4; d <<= 1) {
        float ov0 = __shfl_xor_sync(m, v0, d);
        int   oi0 = __shfl_xor_sync(m, i0, d);
        float ov1 = __shfl_xor_sync(m, v1, d);
        int   oi1 = __shfl_xor_sync(m, i1, d);
        top2_insert(ov0, oi0, v0, i0, v1, i1);
        top2_insert(ov1, oi1, v0, i0, v1, i1);
    }

    if (eb == 0) {
        int tok = t0 + tl;
        float r   = expf(v1 - v0);
        float inv = 1.0f / (1.0f + r);
        int p0 = atomicAdd(&g_cnt[i0], 1);
        g_dst[i0 * B_TOK + p0] = tok * 2;
        g_gw [i0 * B_TOK + p0] = inv;
        int p1 = atomicAdd(&g_cnt[i1], 1);
        g_dst[i1 * B_TOK + p1] = tok * 2 + 1;
        g_gw [i1 * B_TOK + p1] = r * inv;
    }
}

// ---------------- kernel 2: HMMA grouped expert MLP (unchanged, validated) ----------------
// dyn smem (from 1024-aligned base SB), all byte offsets:
//   Hhi @ 0 (18432 = 128 rows * 144B)   Hlo @ 18432          (36864 total)
//   pool @ 36864:
//     Phase A buf b @ pool + b*55296:
//       Xhi(18432: 128r x 144B) Xlo(+18432) W1hi(+36864, 64r x 144B = 9216) W1lo(+46080)
//     Phase B buf b @ pool + b*34816:
//       W2hi(17408: 64r x 272B) W2lo(+17408)
#define SM_POOL 36864
#define SM_DYN  (36864 + 2*55296 + 1024)

__global__ void __launch_bounds__(256, 1) expert_kernel(
    const float* __restrict__ x, const float* __restrict__ b1,
    const float* __restrict__ b2)
{
    const int e    = blockIdx.y;
    const int n    = g_cnt[e];
    const int base = blockIdx.x * TILE_M;
    if (base >= n) return;

    const int tid = threadIdx.x;
    const int wid = tid >> 5, lid = tid & 31;
    const int wm  = wid & 3, wn = wid >> 2;     // warp grid 4(M) x 2(N)

    __shared__ int   s_dst[TILE_M];
    __shared__ int   s_tok[TILE_M];
    __shared__ float s_w[TILE_M];
    extern __shared__ char dynsm[];
    const uint32_t SB = (smem_u32(dynsm) + 1023u) & ~1023u;
    const uint32_t SP = SB + SM_POOL;

    if (tid < TILE_M) {
        int slot = base + tid;
        if (slot < n) {
            int d = g_dst[e * B_TOK + slot];
            s_dst[tid] = d; s_tok[tid] = d >> 1;
            s_w[tid] = g_gw[e * B_TOK + slot];
        } else { s_dst[tid] = -1; s_tok[tid] = 0; s_w[tid] = 0.f; }
    }
    __syncthreads();

    // ================= Phase A: H = relu(X @ W1 + b1) =================
    const int arow = tid >> 1, ahalf = tid & 1;
    const float* xrow = x + (size_t)s_tok[arow] * D_IN + ahalf * 32;
    float4 xr[8];

    auto ldgX = [&](int c) {
        const float* p = xrow + c * 64;
        #pragma unroll
        for (int j = 0; j < 8; j++) xr[j] = *(const float4*)(p + j * 4);
    };
    auto stsX = [&](int b) {
        uint32_t hib = SP + b * 55296;
        uint32_t lob = hib + 18432;
        uint32_t hi[16], lo[16];
        #pragma unroll
        for (int j = 0; j < 8; j++) {
            float f0 = xr[j].x, f1 = xr[j].y, f2 = xr[j].z, f3 = xr[j].w;
            uint32_t h0 = pk_bf(f0, f1), h1 = pk_bf(f2, f3);
            hi[2*j] = h0; hi[2*j+1] = h1;
            lo[2*j]   = pk_bf(f0 - bf_lo_f(h0), f1 - bf_hi_f(h0));
            lo[2*j+1] = pk_bf(f2 - bf_lo_f(h1), f3 - bf_hi_f(h1));
        }
        uint32_t rb = arow * 144 + ahalf * 64;
        #pragma unroll
        for (int q = 0; q < 4; q++) {
            sts128(hib + rb + q * 16, hi[4*q], hi[4*q+1], hi[4*q+2], hi[4*q+3]);
            sts128(lob + rb + q * 16, lo[4*q], lo[4*q+1], lo[4*q+2], lo[4*q+3]);
        }
    };
    auto cpW1 = [&](int c, int b) {
        uint32_t hib = SP + b * 55296 + 36864;
        uint32_t lob = hib + 9216;
        #pragma unroll
        for (int i = 0; i < 2; i++) {
            int f = tid + i * 256;               // 0..511
            int r = f >> 3, s = f & 7;
            uint32_t off = r * 144 + s * 16;
            int gi = (e * D_IN + c * 64 + r) * NH + s * 8;
            cp16s(hib + off, &g_W1s_hi[gi]);
            cp16s(lob + off, &g_W1s_lo[gi]);
        }
    };

    float accA[2][4][4];
    #pragma unroll
    for (int mb = 0; mb < 2; mb++)
        #pragma unroll
        for (int nb = 0; nb < 4; nb++)
            #pragma unroll
            for (int q = 0; q < 4; q++) accA[mb][nb][q] = 0.f;

    auto computeA = [&](int b) {
        uint32_t Xb = SP + b * 55296;
        uint32_t Wb = Xb + 36864;
        #pragma unroll
        for (int ks = 0; ks < 4; ks++) {
            uint32_t ah[2][4], al[2][4];
            #pragma unroll
            for (int mb = 0; mb < 2; mb++) {
                uint32_t ad = Xb + (wm*32 + mb*16 + (lid & 15)) * 144
                            + ks * 32 + ((lid >> 4) << 4);
                ldsm4(ad, ah[mb]);
                ldsm4(ad + 18432, al[mb]);
            }
            #pragma unroll
            for (int j = 0; j < 2; j++) {
                uint32_t bd = Wb + (ks*16 + (lid & 15)) * 144
                            + (wn*32 + j*16 + ((lid >> 4) << 3)) * 2;
                uint32_t bh[4], bl[4];
                ldsm4t(bd, bh);
                ldsm4t(bd + 9216, bl);
                #pragma unroll
                for (int mb = 0; mb < 2; mb++)
                    #pragma unroll
                    for (int nn = 0; nn < 2; nn++) {
                        int nb = j*2 + nn;
                        mma16816(accA[mb][nb], ah[mb], bh + nn*2);
                        mma16816(accA[mb][nb], ah[mb], bl + nn*2);
                        mma16816(accA[mb][nb], al[mb], bh + nn*2);
                    }
            }
        }
    };

    ldgX(0);
    stsX(0);
    cpW1(0, 0); cp_commit();
    ldgX(1);
    cp_wait<0>(); __syncthreads();
    #pragma unroll 1
    for (int c = 0; c < 16; c++) {
        const int b = c & 1;
        if (c < 15) {
            stsX(b ^ 1);                      // xr holds chunk c+1
            cpW1(c + 1, b ^ 1); cp_commit();
            if (c < 14) ldgX(c + 2);
        }
        computeA(b);
        if (c < 15) { cp_wait<0>(); __syncthreads(); }
    }

    // ---- epilogue A: bias + relu -> bf16 hi/lo H tiles ----
    {
        char* SBp = dynsm + (SB - smem_u32(dynsm));
        #pragma unroll
        for (int mb = 0; mb < 2; mb++) {
            int r = wm*32 + mb*16 + (lid >> 2);
            #pragma unroll
            for (int nb = 0; nb < 4; nb++) {
                int col = wn*32 + nb*8 + (lid & 3) * 2;
                float bb0 = b1[e * NH + col], bb1 = b1[e * NH + col + 1];
                float v0 = fmaxf(accA[mb][nb][0] + bb0, 0.f);
                float v1 = fmaxf(accA[mb][nb][1] + bb1, 0.f);
                uint32_t h = pk_bf(v0, v1);
                uint32_t l = pk_bf(v0 - bf_lo_f(h), v1 - bf_hi_f(h));
                *(uint32_t*)(SBp + r * 144 + col * 2)         = h;
                *(uint32_t*)(SBp + 18432 + r * 144 + col * 2) = l;
                v0 = fmaxf(accA[mb][nb][2] + bb0, 0.f);
                v1 = fmaxf(accA[mb][nb][3] + bb1, 0.f);
                h = pk_bf(v0, v1);
                l = pk_bf(v0 - bf_lo_f(h), v1 - bf_hi_f(h));
                *(uint32_t*)(SBp + (r + 8) * 144 + col * 2)         = h;
                *(uint32_t*)(SBp + 18432 + (r + 8) * 144 + col * 2) = l;
            }
        }
    }
    __syncthreads();

    // ================= Phase B: Y = w * (H @ W2 + b2) =================
    auto cpW2 = [&](int cn, int b) {
        uint32_t hib = SP + b * 34816;
        uint32_t lob = hib + 17408;
        #pragma unroll
        for (int i = 0; i < 4; i++) {
            int f = tid + i * 256;               // 0..1023
            int r = f >> 4, s = f & 15;
            uint32_t off = r * 272 + s * 16;
            int gi = (e * NH + r) * D_OUT + cn * 128 + s * 8;
            cp16s(hib + off, &g_W2s_hi[gi]);
            cp16s(lob + off, &g_W2s_lo[gi]);
        }
    };

    cpW2(0, 0); cp_commit();
    cp_wait<0>(); __syncthreads();
    #pragma unroll 1
    for (int cn = 0; cn < 8; cn++) {
        const int b = cn & 1;
        if (cn < 7) { cpW2(cn + 1, b ^ 1); cp_commit(); }

        float accB[2][8][4];
        #pragma unroll
        for (int mb = 0; mb < 2; mb++)
            #pragma unroll
            for (int nb = 0; nb < 8; nb++)
                #pragma unroll
                for (int q = 0; q < 4; q++) accB[mb][nb][q] = 0.f;

        uint32_t Wb = SP + b * 34816;
        #pragma unroll
        for (int ks = 0; ks < 4; ks++) {
            uint32_t ah[2][4], al[2][4];
            #pragma unroll
            for (int mb = 0; mb < 2; mb++) {
                uint32_t ad = SB + (wm*32 + mb*16 + (lid & 15)) * 144
                            + ks * 32 + ((lid >> 4) << 4);
                ldsm4(ad, ah[mb]);
                ldsm4(ad + 18432, al[mb]);
            }
            #pragma unroll
            for (int j = 0; j < 4; j++) {
                uint32_t bd = Wb + (ks*16 + (lid & 15)) * 272
                            + (wn*64 + j*16 + ((lid >> 4) << 3)) * 2;
                uint32_t bh[4], bl[4];
                ldsm4t(bd, bh);
                ldsm4t(bd + 17408, bl);
                #pragma unroll
                for (int mb = 0; mb < 2; mb++)
                    #pragma unroll
                    for (int nn = 0; nn < 2; nn++) {
                        int nb = j*2 + nn;
                        mma16816(accB[mb][nb], ah[mb], bh + nn*2);
                        mma16816(accB[mb][nb], ah[mb], bl + nn*2);
                        mma16816(accB[mb][nb], al[mb], bh + nn*2);
                    }
            }
        }

        // epilogue: + b2, * gate weight, scatter to ybuf slots
        #pragma unroll
        for (int mb = 0; mb < 2; mb++) {
            int r  = wm*32 + mb*16 + (lid >> 2);
            int d0 = s_dst[r],     d1 = s_dst[r + 8];
            float w0 = s_w[r],     w1 = s_w[r + 8];
            #pragma unroll
            for (int nb = 0; nb < 8; nb++) {
                int col = cn*128 + wn*64 + nb*8 + (lid & 3) * 2;
                float bb0 = b2[e * D_OUT + col], bb1 = b2[e * D_OUT + col + 1];
                if (d0 >= 0) {
                    float2 o;
                    o.x = w0 * (accB[mb][nb][0] + bb0);
                    o.y = w0 * (accB[mb][nb][1] + bb1);
                    *(float2*)&g_ybuf[(size_t)d0 * D_OUT + col] = o;
                }
                if (d1 >= 0) {
                    float2 o;
                    o.x = w1 * (accB[mb][nb][2] + bb0);
                    o.y = w1 * (accB[mb][nb][3] + bb1);
                    *(float2*)&g_ybuf[(size_t)d1 * D_OUT + col] = o;
                }
            }
        }
        if (cn < 7) { cp_wait<0>(); __syncthreads(); }
    }
}

// ---------------- kernel 3: combine ----------------
__global__ void __launch_bounds__(256) combine_kernel(float* __restrict__ out) {
    int idx = blockIdx.x * 256 + threadIdx.x;
    int t = idx >> 8;
    int c = idx & 255;
    float4 a = *((const float4*)&g_ybuf[(t * 2    ) * D_OUT] + c);
    float4 b = *((const float4*)&g_ybuf[(t * 2 + 1) * D_OUT] + c);
    float4 r;
    r.x = a.x + b.x; r.y = a.y + b.y; r.z = a.z + b.z; r.w = a.w + b.w;
    ((float4*)out)[idx] = r;
}

// ---------------- launch ----------------
extern "C" void kernel_launch(void* const* d_in, const int* in_sizes, int n_in,
                              void* d_out, int out_size) {
    const float* x  = (const float*)d_in[0];
    const float* Wg = (const float*)d_in[1];
    const float* bg = (const float*)d_in[2];
    const float* W1 = (const float*)d_in[3];
    const float* b1 = (const float*)d_in[4];
    const float* W2 = (const float*)d_in[5];
    const float* b2 = (const float*)d_in[6];
    float* out = (float*)d_out;

    cudaFuncSetAttribute(expert_kernel,
                         cudaFuncAttributeMaxDynamicSharedMemorySize, SM_DYN);

    __nv_bfloat16 *w1hi, *w1lo, *w2hi, *w2lo;
    cudaGetSymbolAddress((void**)&w1hi, g_W1s_hi);
    cudaGetSymbolAddress((void**)&w1lo, g_W1s_lo);
    cudaGetSymbolAddress((void**)&w2hi, g_W2s_hi);
    cudaGetSymbolAddress((void**)&w2lo, g_W2s_lo);

    reset_kernel<<<1, 32>>>();
    const int NW = NE * D_IN * NH;
    split_kernel<<<(NW + 255) / 256, 256>>>(W1, w1hi, w1lo, NW);
    split_kernel<<<(NW + 255) / 256, 256>>>(W2, w2hi, w2lo, NW);
    gate_kernel<<<B_TOK / GT, 128>>>(x, Wg, bg);
    expert_kernel<<<dim3(B_TOK / TILE_M, NE), 256, SM_DYN>>>(x, b1, b2);
    combine_kernel<<<(B_TOK * D_OUT / 4) / 256, 256>>>(out);
}